// round 6
// baseline (speedup 1.0000x reference)
#include <cuda_runtime.h>
#include <cstdint>
#include <mma.h>
using namespace nvcuda;

// Problem constants
#define Bb 2
#define Tt 16
#define Hh 32
#define Ww 32
#define Cc 768
#define NHh 12
#define HDd 64
#define NTOK (Bb*Tt*Hh*Ww)      // 32768
#define F3 (3*Cc)               // 2304

// Scratch (no allocations allowed — device globals)
__device__ float g_y[NTOK * Cc];        // LN output (tf32-rounded)
__device__ float g_qkv[NTOK * F3];      // QKV GEMM output
__device__ float g_o[NTOK * Cc];        // attention output
__device__ float g_wq[F3 * Cc];         // tf32-rounded Wqkv
__device__ float g_wo[Cc * Cc];         // tf32-rounded Wout

// ---------------------------------------------------------------------------
// tf32 rounding pre-pass (float4)
// ---------------------------------------------------------------------------
__global__ void round_tf32_kernel(const float* __restrict__ in,
                                  float* __restrict__ out, int n4) {
    int i = blockIdx.x * 256 + threadIdx.x;
    if (i < n4) {
        float4 v = ((const float4*)in)[i];
        v.x = wmma::__float_to_tf32(v.x);
        v.y = wmma::__float_to_tf32(v.y);
        v.z = wmma::__float_to_tf32(v.z);
        v.w = wmma::__float_to_tf32(v.w);
        ((float4*)out)[i] = v;
    }
}

// ---------------------------------------------------------------------------
// LayerNorm: one block (192 threads) per token; output rounded to tf32
// ---------------------------------------------------------------------------
__global__ void ln_kernel(const float* __restrict__ x,
                          const float* __restrict__ w,
                          const float* __restrict__ b,
                          float* __restrict__ y) {
    int tok = blockIdx.x;
    int t = threadIdx.x;
    const float4* xr = (const float4*)(x + (size_t)tok * Cc);
    float4* yr = (float4*)(y + (size_t)tok * Cc);

    float4 v = xr[t];
    float s  = v.x + v.y + v.z + v.w;
    float ss = v.x*v.x + v.y*v.y + v.z*v.z + v.w*v.w;

    __shared__ float reds[6], redss[6];
    #pragma unroll
    for (int o = 16; o; o >>= 1) {
        s  += __shfl_xor_sync(0xffffffffu, s,  o);
        ss += __shfl_xor_sync(0xffffffffu, ss, o);
    }
    int wid = t >> 5, lid = t & 31;
    if (lid == 0) { reds[wid] = s; redss[wid] = ss; }
    __syncthreads();
    if (t < 32) {
        s  = (lid < 6) ? reds[lid]  : 0.f;
        ss = (lid < 6) ? redss[lid] : 0.f;
        #pragma unroll
        for (int o = 4; o; o >>= 1) {
            s  += __shfl_xor_sync(0xffffffffu, s,  o);
            ss += __shfl_xor_sync(0xffffffffu, ss, o);
        }
        if (lid == 0) { reds[0] = s; redss[0] = ss; }
    }
    __syncthreads();
    float mu  = reds[0] * (1.0f / Cc);
    float var = redss[0] * (1.0f / Cc) - mu * mu;
    float rstd = rsqrtf(var + 1e-5f);

    float4 wv = ((const float4*)w)[t];
    float4 bv = ((const float4*)b)[t];
    float4 r;
    r.x = wmma::__float_to_tf32((v.x - mu) * rstd * wv.x + bv.x);
    r.y = wmma::__float_to_tf32((v.y - mu) * rstd * wv.y + bv.y);
    r.z = wmma::__float_to_tf32((v.z - mu) * rstd * wv.z + bv.z);
    r.w = wmma::__float_to_tf32((v.w - mu) * rstd * wv.w + bv.w);
    yr[t] = r;
}

// ---------------------------------------------------------------------------
// TF32 wmma GEMM, operands pre-rounded to tf32 (no cvt in inner loop).
// C[m,n] = sum_k A[m,k]*Wt[n,k] + bias[n] (+ res[m,n])
// Block 128x128, BK=32, 2-stage cp.async, 8 warps (2 m x 4 n), warp 64x32.
// smem rows padded to 36 floats (144B: 16B-aligned, low bank conflict).
// ---------------------------------------------------------------------------
#define BM 128
#define BN 128
#define BK 32
#define SSTR 36
#define LDC 132
#define STAGE_F (BM * SSTR + BN * SSTR)      // 9216 floats per stage
#define GEMM_SMEM_BYTES (2 * STAGE_F * 4)    // 73728

__device__ __forceinline__ void cp_async16(float* smem_dst, const float* gmem_src) {
    unsigned s = (unsigned)__cvta_generic_to_shared(smem_dst);
    asm volatile("cp.async.cg.shared.global [%0], [%1], 16;\n" :: "r"(s), "l"(gmem_src));
}
#define CP_COMMIT() asm volatile("cp.async.commit_group;\n" ::: "memory")
#define CP_WAIT1()  asm volatile("cp.async.wait_group 1;\n" ::: "memory")
#define CP_WAIT0()  asm volatile("cp.async.wait_group 0;\n" ::: "memory")

template <bool RES>
__global__ void __launch_bounds__(256, 2) gemm_tf32(
        const float* __restrict__ A,
        const float* __restrict__ Wt,
        const float* __restrict__ bias,
        const float* __restrict__ res,
        float* __restrict__ Cout,
        int N, int K) {
    extern __shared__ __align__(16) float smem[];
    float* As[2] = { smem,                 smem + STAGE_F };
    float* Bs[2] = { smem + BM * SSTR,     smem + STAGE_F + BM * SSTR };

    int tid = threadIdx.x;
    int m0 = blockIdx.y * BM;
    int n0 = blockIdx.x * BN;

    // cp.async mapping: 128 rows x 8 16B-chunks = 1024 chunks; 4 per thread
    int lrow = tid >> 1;               // 0..127 (2 threads per row, 4 chunks each)
    int lo   = (tid & 1) * 4;          // chunk offset 0 or 4

    const float* Abase = A  + (size_t)(m0 + lrow) * K + lo * 4;
    const float* Bbase = Wt + (size_t)(n0 + lrow) * K + lo * 4;

    int wid = tid >> 5;
    int wm = (wid & 1) * 64;           // 2 warps in m
    int wn = (wid >> 1) * 32;          // 4 warps in n

    wmma::fragment<wmma::accumulator, 16, 16, 8, float> acc[4][2];
    #pragma unroll
    for (int i = 0; i < 4; i++)
        #pragma unroll
        for (int j = 0; j < 2; j++)
            wmma::fill_fragment(acc[i][j], 0.0f);

    const int nit = K / BK;

    // Prologue: stage 0
    {
        float* a = As[0] + lrow * SSTR + lo * 4;
        float* b = Bs[0] + lrow * SSTR + lo * 4;
        #pragma unroll
        for (int c = 0; c < 4; c++) {
            cp_async16(a + c * 4, Abase + c * 4);
            cp_async16(b + c * 4, Bbase + c * 4);
        }
        CP_COMMIT();
    }

    for (int it = 0; it < nit; it++) {
        if (it + 1 < nit) {
            int st = (it + 1) & 1;
            const float* ag = Abase + (it + 1) * BK;
            const float* bg = Bbase + (it + 1) * BK;
            float* a = As[st] + lrow * SSTR + lo * 4;
            float* b = Bs[st] + lrow * SSTR + lo * 4;
            #pragma unroll
            for (int c = 0; c < 4; c++) {
                cp_async16(a + c * 4, ag + c * 4);
                cp_async16(b + c * 4, bg + c * 4);
            }
            CP_COMMIT();
            CP_WAIT1();
        } else {
            CP_WAIT0();
        }
        __syncthreads();

        int cur = it & 1;
        float* Ac = As[cur];
        float* Bc = Bs[cur];
        #pragma unroll
        for (int kk = 0; kk < BK; kk += 8) {
            wmma::fragment<wmma::matrix_a, 16, 16, 8, wmma::precision::tf32, wmma::row_major> af[4];
            wmma::fragment<wmma::matrix_b, 16, 16, 8, wmma::precision::tf32, wmma::col_major> bf[2];
            #pragma unroll
            for (int i = 0; i < 4; i++)
                wmma::load_matrix_sync(af[i], &Ac[(wm + i * 16) * SSTR + kk], SSTR);
            #pragma unroll
            for (int j = 0; j < 2; j++)
                wmma::load_matrix_sync(bf[j], &Bc[(wn + j * 16) * SSTR + kk], SSTR);
            #pragma unroll
            for (int i = 0; i < 4; i++)
                #pragma unroll
                for (int j = 0; j < 2; j++)
                    wmma::mma_sync(acc[i][j], af[i], bf[j], acc[i][j]);
        }
        __syncthreads();
    }

    // Epilogue through shared (reuse smem; 128*132=16896 floats <= 18432)
    float* Cs = smem;
    #pragma unroll
    for (int i = 0; i < 4; i++)
        #pragma unroll
        for (int j = 0; j < 2; j++)
            wmma::store_matrix_sync(&Cs[(wm + i * 16) * LDC + wn + j * 16],
                                    acc[i][j], LDC, wmma::mem_row_major);
    __syncthreads();

    #pragma unroll
    for (int i = 0; i < 16; i++) {
        int idx = tid + i * 256;
        int r = idx >> 5, c4 = idx & 31;
        const float* cs = &Cs[r * LDC + c4 * 4];
        float4 bv = *(const float4*)(bias + n0 + c4 * 4);
        float4 v;
        v.x = cs[0] + bv.x; v.y = cs[1] + bv.y;
        v.z = cs[2] + bv.z; v.w = cs[3] + bv.w;
        size_t g = (size_t)(m0 + r) * N + n0 + c4 * 4;
        if (RES) {
            float4 rv = *(const float4*)(res + g);
            v.x += rv.x; v.y += rv.y; v.z += rv.z; v.w += rv.w;
        }
        *(float4*)(Cout + g) = v;
    }
}

// ---------------------------------------------------------------------------
// Attention over time axis: one warp per (b,h,w,head) unit. T=16, HD=64.
// ---------------------------------------------------------------------------
#define QSTR 68
__global__ void attn_kernel(const float* __restrict__ qkv, float* __restrict__ o) {
    int warp_in_blk = threadIdx.x >> 5;
    int lane = threadIdx.x & 31;
    int unit = blockIdx.x * 2 + warp_in_blk;   // 2 warps per block

    __shared__ float sm[2][3 * 16 * QSTR + 256];
    float* q = sm[warp_in_blk];
    float* k = q + 16 * QSTR;
    float* v = k + 16 * QSTR;
    float* p = v + 16 * QSTR;                  // 16x16 probs

    int head = unit % NHh;
    int s = unit / NHh;
    int w = s & 31; s >>= 5;
    int h = s & 31;
    int b = s >> 5;

    int spatial = h * 32 + w;
    int fofs = head * 192;

    // Load q,k,v (T=16 x HD=64 each)
    for (int idx = lane; idx < 16 * 64; idx += 32) {
        int t = idx >> 6, d = idx & 63;
        size_t g = (size_t)((b * 16 + t) * 1024 + spatial) * F3 + fofs + d;
        q[t * QSTR + d] = qkv[g];
        k[t * QSTR + d] = qkv[g + 64];
        v[t * QSTR + d] = qkv[g + 128];
    }
    __syncwarp();

    // Scores: lane pair (2 lanes per tq), each lane does 8 tk
    int tq = lane >> 1;
    int tk0 = (lane & 1) * 8;
    float sc[8];
    #pragma unroll
    for (int j = 0; j < 8; j++) {
        float acc = 0.f;
        #pragma unroll
        for (int d = 0; d < 64; d++)
            acc += q[tq * QSTR + d] * k[(tk0 + j) * QSTR + d];
        sc[j] = acc * 0.125f;   // 1/sqrt(64)
    }
    float m = sc[0];
    #pragma unroll
    for (int j = 1; j < 8; j++) m = fmaxf(m, sc[j]);
    m = fmaxf(m, __shfl_xor_sync(0xffffffffu, m, 1));
    float sum = 0.f;
    #pragma unroll
    for (int j = 0; j < 8; j++) { sc[j] = __expf(sc[j] - m); sum += sc[j]; }
    sum += __shfl_xor_sync(0xffffffffu, sum, 1);
    float inv = 1.0f / sum;
    #pragma unroll
    for (int j = 0; j < 8; j++) p[tq * 16 + tk0 + j] = sc[j] * inv;
    __syncwarp();

    // o[t,d] = sum_tk p[t,tk] * v[tk,d]
    for (int idx = lane; idx < 16 * 64; idx += 32) {
        int t = idx >> 6, d = idx & 63;
        float acc = 0.f;
        #pragma unroll
        for (int tk = 0; tk < 16; tk++)
            acc += p[t * 16 + tk] * v[tk * QSTR + d];
        size_t g = (size_t)((b * 16 + t) * 1024 + spatial) * Cc + head * 64 + d;
        o[g] = acc;
    }
}

// ---------------------------------------------------------------------------
// Launch
// ---------------------------------------------------------------------------
extern "C" void kernel_launch(void* const* d_in, const int* in_sizes, int n_in,
                              void* d_out, int out_size) {
    const float* x     = (const float*)d_in[0];
    const float* ln1_w = (const float*)d_in[1];
    const float* ln1_b = (const float*)d_in[2];
    const float* Wqkv  = (const float*)d_in[3];
    const float* bqkv  = (const float*)d_in[4];
    const float* ln2_w = (const float*)d_in[5];
    const float* ln2_b = (const float*)d_in[6];
    const float* Wout  = (const float*)d_in[7];
    const float* bout  = (const float*)d_in[8];
    float* out = (float*)d_out;

    static float *p_y = nullptr, *p_qkv = nullptr, *p_o = nullptr,
                 *p_wq = nullptr, *p_wo = nullptr;
    if (!p_y) {
        cudaGetSymbolAddress((void**)&p_y, g_y);
        cudaGetSymbolAddress((void**)&p_qkv, g_qkv);
        cudaGetSymbolAddress((void**)&p_o, g_o);
        cudaGetSymbolAddress((void**)&p_wq, g_wq);
        cudaGetSymbolAddress((void**)&p_wo, g_wo);
        cudaFuncSetAttribute(gemm_tf32<false>,
                             cudaFuncAttributeMaxDynamicSharedMemorySize, GEMM_SMEM_BYTES);
        cudaFuncSetAttribute(gemm_tf32<true>,
                             cudaFuncAttributeMaxDynamicSharedMemorySize, GEMM_SMEM_BYTES);
    }

    // 0) tf32-round weights
    {
        int n4q = (F3 * Cc) / 4, n4o = (Cc * Cc) / 4;
        round_tf32_kernel<<<(n4q + 255) / 256, 256>>>(Wqkv, p_wq, n4q);
        round_tf32_kernel<<<(n4o + 255) / 256, 256>>>(Wout, p_wo, n4o);
    }

    // 1) LN1 (rounds output to tf32)
    ln_kernel<<<NTOK, 192>>>(x, ln1_w, ln1_b, p_y);

    // 2) QKV GEMM: (32768 x 2304)
    {
        dim3 grid(F3 / BN, NTOK / BM);     // 18 x 256
        gemm_tf32<false><<<grid, 256, GEMM_SMEM_BYTES>>>(p_y, p_wq, bqkv,
                                                         nullptr, p_qkv, F3, Cc);
    }

    // 3) Attention over time, per (b,h,w,head)
    {
        int nunits = Bb * Hh * Ww * NHh;   // 24576
        attn_kernel<<<nunits / 2, 64>>>(p_qkv, p_o);
    }

    // 4) LN2 (reuse g_y)
    ln_kernel<<<NTOK, 192>>>(p_o, ln2_w, ln2_b, p_y);

    // 5) Out GEMM + bias + residual: (32768 x 768)
    {
        dim3 grid(Cc / BN, NTOK / BM);     // 6 x 256
        gemm_tf32<true><<<grid, 256, GEMM_SMEM_BYTES>>>(p_y, p_wo, bout,
                                                        x, out, Cc, Cc);
    }
}

// round 7
// speedup vs baseline: 2.8482x; 2.8482x over previous
#include <cuda_runtime.h>
#include <cstdint>
#include <cuda_fp16.h>
#include <mma.h>
using namespace nvcuda;

// Problem constants
#define Bb 2
#define Tt 16
#define Hh 32
#define Ww 32
#define Cc 768
#define NHh 12
#define HDd 64
#define NTOK (Bb*Tt*Hh*Ww)      // 32768
#define F3 (3*Cc)               // 2304

// Scratch (no allocations allowed — device globals)
__device__ __half g_yh[NTOK * Cc];      // LN output (half)
__device__ float  g_qkv[NTOK * F3];     // QKV GEMM output (fp32)
__device__ float  g_o[NTOK * Cc];       // attention output (fp32)
__device__ __half g_wqh[F3 * Cc];       // half Wqkv
__device__ __half g_woh[Cc * Cc];       // half Wout

// ---------------------------------------------------------------------------
// float -> half conversion pre-pass (float4 -> 4 halfs)
// ---------------------------------------------------------------------------
__global__ void f2h_kernel(const float* __restrict__ in,
                           __half* __restrict__ out, int n4) {
    int i = blockIdx.x * 256 + threadIdx.x;
    if (i < n4) {
        float4 v = ((const float4*)in)[i];
        __half2 a = __floats2half2_rn(v.x, v.y);
        __half2 b = __floats2half2_rn(v.z, v.w);
        ((__half2*)out)[2 * i]     = a;
        ((__half2*)out)[2 * i + 1] = b;
    }
}

// ---------------------------------------------------------------------------
// LayerNorm: one block (192 threads) per token; output in fp16
// ---------------------------------------------------------------------------
__global__ void ln_kernel(const float* __restrict__ x,
                          const float* __restrict__ w,
                          const float* __restrict__ b,
                          __half* __restrict__ y) {
    int tok = blockIdx.x;
    int t = threadIdx.x;
    const float4* xr = (const float4*)(x + (size_t)tok * Cc);
    __half2* yr = (__half2*)(y + (size_t)tok * Cc);

    float4 v = xr[t];
    float s  = v.x + v.y + v.z + v.w;
    float ss = v.x*v.x + v.y*v.y + v.z*v.z + v.w*v.w;

    __shared__ float reds[6], redss[6];
    #pragma unroll
    for (int o = 16; o; o >>= 1) {
        s  += __shfl_xor_sync(0xffffffffu, s,  o);
        ss += __shfl_xor_sync(0xffffffffu, ss, o);
    }
    int wid = t >> 5, lid = t & 31;
    if (lid == 0) { reds[wid] = s; redss[wid] = ss; }
    __syncthreads();
    if (t < 32) {
        s  = (lid < 6) ? reds[lid]  : 0.f;
        ss = (lid < 6) ? redss[lid] : 0.f;
        #pragma unroll
        for (int o = 4; o; o >>= 1) {
            s  += __shfl_xor_sync(0xffffffffu, s,  o);
            ss += __shfl_xor_sync(0xffffffffu, ss, o);
        }
        if (lid == 0) { reds[0] = s; redss[0] = ss; }
    }
    __syncthreads();
    float mu  = reds[0] * (1.0f / Cc);
    float var = redss[0] * (1.0f / Cc) - mu * mu;
    float rstd = rsqrtf(var + 1e-5f);

    float4 wv = ((const float4*)w)[t];
    float4 bv = ((const float4*)b)[t];
    float rx = (v.x - mu) * rstd * wv.x + bv.x;
    float ry = (v.y - mu) * rstd * wv.y + bv.y;
    float rz = (v.z - mu) * rstd * wv.z + bv.z;
    float rw = (v.w - mu) * rstd * wv.w + bv.w;
    yr[2 * t]     = __floats2half2_rn(rx, ry);
    yr[2 * t + 1] = __floats2half2_rn(rz, rw);
}

// ---------------------------------------------------------------------------
// FP16 wmma GEMM (fp32 accumulate).
// C[m,n] = sum_k A[m,k]*Wt[n,k] + bias[n] (+ res[m,n])
// Block 128x128, BK=32 halfs, 2-stage cp.async, 8 warps (2m x 4n), warp 64x32.
// smem rows padded to 40 halfs (80B).
// ---------------------------------------------------------------------------
#define BM 128
#define BN 128
#define BKH 32
#define SSTRH 40
#define LDC 132
#define STAGE_H ((BM + BN) * SSTRH)            // 10240 halfs = 20480 B
#define PIPE_BYTES (2 * STAGE_H * 2)           // 40960
#define EPI_BYTES (BM * LDC * 4)               // 67584
#define GEMM_SMEM_BYTES EPI_BYTES

__device__ __forceinline__ void cp_async16(void* smem_dst, const void* gmem_src) {
    unsigned s = (unsigned)__cvta_generic_to_shared(smem_dst);
    asm volatile("cp.async.cg.shared.global [%0], [%1], 16;\n" :: "r"(s), "l"(gmem_src));
}
#define CP_COMMIT() asm volatile("cp.async.commit_group;\n" ::: "memory")
#define CP_WAIT1()  asm volatile("cp.async.wait_group 1;\n" ::: "memory")
#define CP_WAIT0()  asm volatile("cp.async.wait_group 0;\n" ::: "memory")

template <bool RES>
__global__ void __launch_bounds__(256, 2) gemm_fp16(
        const __half* __restrict__ A,
        const __half* __restrict__ Wt,
        const float* __restrict__ bias,
        const float* __restrict__ res,
        float* __restrict__ Cout,
        int N, int K) {
    extern __shared__ __align__(16) char smem_raw[];
    __half* hs = (__half*)smem_raw;
    __half* As[2] = { hs,                     hs + STAGE_H };
    __half* Bs[2] = { hs + BM * SSTRH,        hs + STAGE_H + BM * SSTRH };

    int tid = threadIdx.x;
    int m0 = blockIdx.y * BM;
    int n0 = blockIdx.x * BN;

    // load mapping: per tile 128 rows x 4 chunks (8 halfs). 512 chunks, 2/thread.
    int lrow = tid >> 1;                 // 0..127
    int lc0  = (tid & 1) * 2;            // chunk 0/1 or 2/3

    const __half* Abase = A  + (size_t)(m0 + lrow) * K + lc0 * 8;
    const __half* Bbase = Wt + (size_t)(n0 + lrow) * K + lc0 * 8;

    int wid = tid >> 5;
    int wm = (wid & 1) * 64;             // 2 warps m
    int wn = (wid >> 1) * 32;            // 4 warps n

    wmma::fragment<wmma::accumulator, 16, 16, 16, float> acc[4][2];
    #pragma unroll
    for (int i = 0; i < 4; i++)
        #pragma unroll
        for (int j = 0; j < 2; j++)
            wmma::fill_fragment(acc[i][j], 0.0f);

    const int nit = K / BKH;             // 24

    // Prologue: stage 0
    {
        __half* a = As[0] + lrow * SSTRH + lc0 * 8;
        __half* b = Bs[0] + lrow * SSTRH + lc0 * 8;
        #pragma unroll
        for (int c = 0; c < 2; c++) {
            cp_async16(a + c * 8, Abase + c * 8);
            cp_async16(b + c * 8, Bbase + c * 8);
        }
        CP_COMMIT();
    }

    for (int it = 0; it < nit; it++) {
        if (it + 1 < nit) {
            int st = (it + 1) & 1;
            const __half* ag = Abase + (it + 1) * BKH;
            const __half* bg = Bbase + (it + 1) * BKH;
            __half* a = As[st] + lrow * SSTRH + lc0 * 8;
            __half* b = Bs[st] + lrow * SSTRH + lc0 * 8;
            #pragma unroll
            for (int c = 0; c < 2; c++) {
                cp_async16(a + c * 8, ag + c * 8);
                cp_async16(b + c * 8, bg + c * 8);
            }
            CP_COMMIT();
            CP_WAIT1();
        } else {
            CP_WAIT0();
        }
        __syncthreads();

        int cur = it & 1;
        __half* Ac = As[cur];
        __half* Bc = Bs[cur];
        #pragma unroll
        for (int kk = 0; kk < BKH; kk += 16) {
            wmma::fragment<wmma::matrix_a, 16, 16, 16, __half, wmma::row_major> af[4];
            wmma::fragment<wmma::matrix_b, 16, 16, 16, __half, wmma::col_major> bf[2];
            #pragma unroll
            for (int i = 0; i < 4; i++)
                wmma::load_matrix_sync(af[i], &Ac[(wm + i * 16) * SSTRH + kk], SSTRH);
            #pragma unroll
            for (int j = 0; j < 2; j++)
                wmma::load_matrix_sync(bf[j], &Bc[(wn + j * 16) * SSTRH + kk], SSTRH);
            #pragma unroll
            for (int i = 0; i < 4; i++)
                #pragma unroll
                for (int j = 0; j < 2; j++)
                    wmma::mma_sync(acc[i][j], af[i], bf[j], acc[i][j]);
        }
        __syncthreads();
    }

    // Epilogue through shared (fp32)
    float* Cs = (float*)smem_raw;
    #pragma unroll
    for (int i = 0; i < 4; i++)
        #pragma unroll
        for (int j = 0; j < 2; j++)
            wmma::store_matrix_sync(&Cs[(wm + i * 16) * LDC + wn + j * 16],
                                    acc[i][j], LDC, wmma::mem_row_major);
    __syncthreads();

    #pragma unroll
    for (int i = 0; i < 16; i++) {
        int idx = tid + i * 256;
        int r = idx >> 5, c4 = idx & 31;
        const float* cs = &Cs[r * LDC + c4 * 4];
        float4 bv = *(const float4*)(bias + n0 + c4 * 4);
        float4 v;
        v.x = cs[0] + bv.x; v.y = cs[1] + bv.y;
        v.z = cs[2] + bv.z; v.w = cs[3] + bv.w;
        size_t g = (size_t)(m0 + r) * N + n0 + c4 * 4;
        if (RES) {
            float4 rv = *(const float4*)(res + g);
            v.x += rv.x; v.y += rv.y; v.z += rv.z; v.w += rv.w;
        }
        *(float4*)(Cout + g) = v;
    }
}

// ---------------------------------------------------------------------------
// Attention over time axis: one warp per (b,h,w,head) unit. T=16, HD=64.
// ---------------------------------------------------------------------------
#define QSTR 68
__global__ void attn_kernel(const float* __restrict__ qkv, float* __restrict__ o) {
    int warp_in_blk = threadIdx.x >> 5;
    int lane = threadIdx.x & 31;
    int unit = blockIdx.x * 2 + warp_in_blk;   // 2 warps per block

    __shared__ float sm[2][3 * 16 * QSTR + 256];
    float* q = sm[warp_in_blk];
    float* k = q + 16 * QSTR;
    float* v = k + 16 * QSTR;
    float* p = v + 16 * QSTR;                  // 16x16 probs

    int head = unit % NHh;
    int s = unit / NHh;
    int w = s & 31; s >>= 5;
    int h = s & 31;
    int b = s >> 5;

    int spatial = h * 32 + w;
    int fofs = head * 192;

    // Load q,k,v (T=16 x HD=64 each)
    for (int idx = lane; idx < 16 * 64; idx += 32) {
        int t = idx >> 6, d = idx & 63;
        size_t g = (size_t)((b * 16 + t) * 1024 + spatial) * F3 + fofs + d;
        q[t * QSTR + d] = qkv[g];
        k[t * QSTR + d] = qkv[g + 64];
        v[t * QSTR + d] = qkv[g + 128];
    }
    __syncwarp();

    // Scores: lane pair (2 lanes per tq), each lane does 8 tk
    int tq = lane >> 1;
    int tk0 = (lane & 1) * 8;
    float sc[8];
    #pragma unroll
    for (int j = 0; j < 8; j++) {
        float acc = 0.f;
        #pragma unroll
        for (int d = 0; d < 64; d++)
            acc += q[tq * QSTR + d] * k[(tk0 + j) * QSTR + d];
        sc[j] = acc * 0.125f;   // 1/sqrt(64)
    }
    float m = sc[0];
    #pragma unroll
    for (int j = 1; j < 8; j++) m = fmaxf(m, sc[j]);
    m = fmaxf(m, __shfl_xor_sync(0xffffffffu, m, 1));
    float sum = 0.f;
    #pragma unroll
    for (int j = 0; j < 8; j++) { sc[j] = __expf(sc[j] - m); sum += sc[j]; }
    sum += __shfl_xor_sync(0xffffffffu, sum, 1);
    float inv = 1.0f / sum;
    #pragma unroll
    for (int j = 0; j < 8; j++) p[tq * 16 + tk0 + j] = sc[j] * inv;
    __syncwarp();

    // o[t,d] = sum_tk p[t,tk] * v[tk,d]
    for (int idx = lane; idx < 16 * 64; idx += 32) {
        int t = idx >> 6, d = idx & 63;
        float acc = 0.f;
        #pragma unroll
        for (int tk = 0; tk < 16; tk++)
            acc += p[t * 16 + tk] * v[tk * QSTR + d];
        size_t g = (size_t)((b * 16 + t) * 1024 + spatial) * Cc + head * 64 + d;
        o[g] = acc;
    }
}

// ---------------------------------------------------------------------------
// Launch
// ---------------------------------------------------------------------------
extern "C" void kernel_launch(void* const* d_in, const int* in_sizes, int n_in,
                              void* d_out, int out_size) {
    const float* x     = (const float*)d_in[0];
    const float* ln1_w = (const float*)d_in[1];
    const float* ln1_b = (const float*)d_in[2];
    const float* Wqkv  = (const float*)d_in[3];
    const float* bqkv  = (const float*)d_in[4];
    const float* ln2_w = (const float*)d_in[5];
    const float* ln2_b = (const float*)d_in[6];
    const float* Wout  = (const float*)d_in[7];
    const float* bout  = (const float*)d_in[8];
    float* out = (float*)d_out;

    static __half *p_yh = nullptr, *p_wqh = nullptr, *p_woh = nullptr;
    static float *p_qkv = nullptr, *p_o = nullptr;
    if (!p_yh) {
        cudaGetSymbolAddress((void**)&p_yh, g_yh);
        cudaGetSymbolAddress((void**)&p_qkv, g_qkv);
        cudaGetSymbolAddress((void**)&p_o, g_o);
        cudaGetSymbolAddress((void**)&p_wqh, g_wqh);
        cudaGetSymbolAddress((void**)&p_woh, g_woh);
        cudaFuncSetAttribute(gemm_fp16<false>,
                             cudaFuncAttributeMaxDynamicSharedMemorySize, GEMM_SMEM_BYTES);
        cudaFuncSetAttribute(gemm_fp16<true>,
                             cudaFuncAttributeMaxDynamicSharedMemorySize, GEMM_SMEM_BYTES);
    }

    // 0) weights -> half
    {
        int n4q = (F3 * Cc) / 4, n4o = (Cc * Cc) / 4;
        f2h_kernel<<<(n4q + 255) / 256, 256>>>(Wqkv, p_wqh, n4q);
        f2h_kernel<<<(n4o + 255) / 256, 256>>>(Wout, p_woh, n4o);
    }

    // 1) LN1 -> half
    ln_kernel<<<NTOK, 192>>>(x, ln1_w, ln1_b, p_yh);

    // 2) QKV GEMM: (32768 x 2304)
    {
        dim3 grid(F3 / BN, NTOK / BM);     // 18 x 256
        gemm_fp16<false><<<grid, 256, GEMM_SMEM_BYTES>>>(p_yh, p_wqh, bqkv,
                                                         nullptr, p_qkv, F3, Cc);
    }

    // 3) Attention over time, per (b,h,w,head)
    {
        int nunits = Bb * Hh * Ww * NHh;   // 24576
        attn_kernel<<<nunits / 2, 64>>>(p_qkv, p_o);
    }

    // 4) LN2 -> half
    ln_kernel<<<NTOK, 192>>>(p_o, ln2_w, ln2_b, p_yh);

    // 5) Out GEMM + bias + residual: (32768 x 768)
    {
        dim3 grid(Cc / BN, NTOK / BM);     // 6 x 256
        gemm_fp16<true><<<grid, 256, GEMM_SMEM_BYTES>>>(p_yh, p_woh, bout,
                                                        x, out, Cc, Cc);
    }
}

// round 8
// speedup vs baseline: 3.3815x; 1.1872x over previous
#include <cuda_runtime.h>
#include <cstdint>
#include <cuda_fp16.h>
#include <mma.h>
using namespace nvcuda;

// Problem constants
#define Bb 2
#define Tt 16
#define Hh 32
#define Ww 32
#define Cc 768
#define NHh 12
#define HDd 64
#define NTOK (Bb*Tt*Hh*Ww)      // 32768
#define F3 (3*Cc)               // 2304

// Scratch (no allocations allowed — device globals)
__device__ __half g_yh[NTOK * Cc];      // LN output (half)
__device__ float  g_qkv[NTOK * F3];     // QKV GEMM output (fp32)
__device__ float  g_o[NTOK * Cc];       // attention output (fp32)
__device__ __half g_wqh[F3 * Cc];       // half Wqkv
__device__ __half g_woh[Cc * Cc];       // half Wout

// ---------------------------------------------------------------------------
// float -> half conversion pre-pass (float4 -> 4 halfs)
// ---------------------------------------------------------------------------
__global__ void f2h_kernel(const float* __restrict__ in,
                           __half* __restrict__ out, int n4) {
    int i = blockIdx.x * 256 + threadIdx.x;
    if (i < n4) {
        float4 v = ((const float4*)in)[i];
        ((__half2*)out)[2 * i]     = __floats2half2_rn(v.x, v.y);
        ((__half2*)out)[2 * i + 1] = __floats2half2_rn(v.z, v.w);
    }
}

// ---------------------------------------------------------------------------
// LayerNorm: one block (192 threads) per token; output in fp16
// ---------------------------------------------------------------------------
__global__ void ln_kernel(const float* __restrict__ x,
                          const float* __restrict__ w,
                          const float* __restrict__ b,
                          __half* __restrict__ y) {
    int tok = blockIdx.x;
    int t = threadIdx.x;
    const float4* xr = (const float4*)(x + (size_t)tok * Cc);
    __half2* yr = (__half2*)(y + (size_t)tok * Cc);

    float4 v = xr[t];
    float s  = v.x + v.y + v.z + v.w;
    float ss = v.x*v.x + v.y*v.y + v.z*v.z + v.w*v.w;

    __shared__ float reds[6], redss[6];
    #pragma unroll
    for (int o = 16; o; o >>= 1) {
        s  += __shfl_xor_sync(0xffffffffu, s,  o);
        ss += __shfl_xor_sync(0xffffffffu, ss, o);
    }
    int wid = t >> 5, lid = t & 31;
    if (lid == 0) { reds[wid] = s; redss[wid] = ss; }
    __syncthreads();
    if (t < 32) {
        s  = (lid < 6) ? reds[lid]  : 0.f;
        ss = (lid < 6) ? redss[lid] : 0.f;
        #pragma unroll
        for (int o = 4; o; o >>= 1) {
            s  += __shfl_xor_sync(0xffffffffu, s,  o);
            ss += __shfl_xor_sync(0xffffffffu, ss, o);
        }
        if (lid == 0) { reds[0] = s; redss[0] = ss; }
    }
    __syncthreads();
    float mu  = reds[0] * (1.0f / Cc);
    float var = redss[0] * (1.0f / Cc) - mu * mu;
    float rstd = rsqrtf(var + 1e-5f);

    float4 wv = ((const float4*)w)[t];
    float4 bv = ((const float4*)b)[t];
    float rx = (v.x - mu) * rstd * wv.x + bv.x;
    float ry = (v.y - mu) * rstd * wv.y + bv.y;
    float rz = (v.z - mu) * rstd * wv.z + bv.z;
    float rw = (v.w - mu) * rstd * wv.w + bv.w;
    yr[2 * t]     = __floats2half2_rn(rx, ry);
    yr[2 * t + 1] = __floats2half2_rn(rz, rw);
}

// ---------------------------------------------------------------------------
// FP16 wmma GEMM (fp32 accumulate), 3-stage cp.async, 1 barrier/iter.
// C[m,n] = sum_k A[m,k]*Wt[n,k] + bias[n] (+ res[m,n])
// Block 128x128, BK=32 halfs, 8 warps (2m x 4n), warp 64x32.
// ---------------------------------------------------------------------------
#define BM 128
#define BN 128
#define BKH 32
#define SSTRH 40
#define LDC 132
#define STAGES 3
#define STAGE_H ((BM + BN) * SSTRH)            // 10240 halfs = 20480 B
#define PIPE_BYTES (STAGES * STAGE_H * 2)      // 61440
#define EPI_BYTES (BM * LDC * 4)               // 67584
#define GEMM_SMEM_BYTES (EPI_BYTES > PIPE_BYTES ? EPI_BYTES : PIPE_BYTES)

__device__ __forceinline__ void cp_async16(void* smem_dst, const void* gmem_src) {
    unsigned s = (unsigned)__cvta_generic_to_shared(smem_dst);
    asm volatile("cp.async.cg.shared.global [%0], [%1], 16;\n" :: "r"(s), "l"(gmem_src));
}
#define CP_COMMIT() asm volatile("cp.async.commit_group;\n" ::: "memory")
#define CP_WAIT_N(n) asm volatile("cp.async.wait_group %0;\n" :: "n"(n) : "memory")

template <bool RES>
__global__ void __launch_bounds__(256, 2) gemm_fp16(
        const __half* __restrict__ A,
        const __half* __restrict__ Wt,
        const float* __restrict__ bias,
        const float* __restrict__ res,
        float* __restrict__ Cout,
        int N, int K) {
    extern __shared__ __align__(16) char smem_raw[];
    __half* hs = (__half*)smem_raw;

    int tid = threadIdx.x;
    int m0 = blockIdx.y * BM;
    int n0 = blockIdx.x * BN;

    // load mapping: per tile 128 rows x 4 chunks (8 halfs each). 2 chunks/thread.
    int lrow = tid >> 1;                 // 0..127
    int lc0  = (tid & 1) * 2;            // chunk pair

    const __half* Abase = A  + (size_t)(m0 + lrow) * K + lc0 * 8;
    const __half* Bbase = Wt + (size_t)(n0 + lrow) * K + lc0 * 8;

    int wid = tid >> 5;
    int wm = (wid & 1) * 64;             // 2 warps m
    int wn = (wid >> 1) * 32;            // 4 warps n

    wmma::fragment<wmma::accumulator, 16, 16, 16, float> acc[4][2];
    #pragma unroll
    for (int i = 0; i < 4; i++)
        #pragma unroll
        for (int j = 0; j < 2; j++)
            wmma::fill_fragment(acc[i][j], 0.0f);

    const int nit = K / BKH;             // 24

    // Prologue: issue stages 0..STAGES-2
    #pragma unroll
    for (int s = 0; s < STAGES - 1; s++) {
        __half* a = hs + s * STAGE_H + lrow * SSTRH + lc0 * 8;
        __half* b = hs + s * STAGE_H + BM * SSTRH + lrow * SSTRH + lc0 * 8;
        const __half* ag = Abase + s * BKH;
        const __half* bg = Bbase + s * BKH;
        #pragma unroll
        for (int c = 0; c < 2; c++) {
            cp_async16(a + c * 8, ag + c * 8);
            cp_async16(b + c * 8, bg + c * 8);
        }
        CP_COMMIT();
    }

    int sc_ = 0, sl_ = STAGES - 1;       // compute stage, next load stage
    for (int it = 0; it < nit; it++) {
        CP_WAIT_N(STAGES - 2);
        __syncthreads();

        // Issue loads for tile it+STAGES-1 into stage sl_ (freed at it-1, safe
        // after the barrier above).
        if (it + STAGES - 1 < nit) {
            __half* a = hs + sl_ * STAGE_H + lrow * SSTRH + lc0 * 8;
            __half* b = hs + sl_ * STAGE_H + BM * SSTRH + lrow * SSTRH + lc0 * 8;
            const __half* ag = Abase + (it + STAGES - 1) * BKH;
            const __half* bg = Bbase + (it + STAGES - 1) * BKH;
            #pragma unroll
            for (int c = 0; c < 2; c++) {
                cp_async16(a + c * 8, ag + c * 8);
                cp_async16(b + c * 8, bg + c * 8);
            }
        }
        CP_COMMIT();                     // commit even if empty (keeps count)

        __half* Ac = hs + sc_ * STAGE_H;
        __half* Bc = Ac + BM * SSTRH;
        #pragma unroll
        for (int kk = 0; kk < BKH; kk += 16) {
            wmma::fragment<wmma::matrix_a, 16, 16, 16, __half, wmma::row_major> af[4];
            wmma::fragment<wmma::matrix_b, 16, 16, 16, __half, wmma::col_major> bf[2];
            #pragma unroll
            for (int i = 0; i < 4; i++)
                wmma::load_matrix_sync(af[i], &Ac[(wm + i * 16) * SSTRH + kk], SSTRH);
            #pragma unroll
            for (int j = 0; j < 2; j++)
                wmma::load_matrix_sync(bf[j], &Bc[(wn + j * 16) * SSTRH + kk], SSTRH);
            #pragma unroll
            for (int i = 0; i < 4; i++)
                #pragma unroll
                for (int j = 0; j < 2; j++)
                    wmma::mma_sync(acc[i][j], af[i], bf[j], acc[i][j]);
        }

        sc_ = (sc_ + 1 == STAGES) ? 0 : sc_ + 1;
        sl_ = (sl_ + 1 == STAGES) ? 0 : sl_ + 1;
    }
    CP_WAIT_N(0);
    __syncthreads();

    // Epilogue through shared (fp32)
    float* Cs = (float*)smem_raw;
    #pragma unroll
    for (int i = 0; i < 4; i++)
        #pragma unroll
        for (int j = 0; j < 2; j++)
            wmma::store_matrix_sync(&Cs[(wm + i * 16) * LDC + wn + j * 16],
                                    acc[i][j], LDC, wmma::mem_row_major);
    __syncthreads();

    #pragma unroll
    for (int i = 0; i < 16; i++) {
        int idx = tid + i * 256;
        int r = idx >> 5, c4 = idx & 31;
        const float* cs = &Cs[r * LDC + c4 * 4];
        float4 bv = *(const float4*)(bias + n0 + c4 * 4);
        float4 v;
        v.x = cs[0] + bv.x; v.y = cs[1] + bv.y;
        v.z = cs[2] + bv.z; v.w = cs[3] + bv.w;
        size_t g = (size_t)(m0 + r) * N + n0 + c4 * 4;
        if (RES) {
            float4 rv = *(const float4*)(res + g);
            v.x += rv.x; v.y += rv.y; v.z += rv.z; v.w += rv.w;
        }
        *(float4*)(Cout + g) = v;
    }
}

// ---------------------------------------------------------------------------
// Attention over time axis: one warp per (b,h,w,head) unit. T=16, HD=64.
// ---------------------------------------------------------------------------
#define QSTR 68
__global__ void attn_kernel(const float* __restrict__ qkv, float* __restrict__ o) {
    int warp_in_blk = threadIdx.x >> 5;
    int lane = threadIdx.x & 31;
    int unit = blockIdx.x * 2 + warp_in_blk;   // 2 warps per block

    __shared__ float sm[2][3 * 16 * QSTR + 256];
    float* q = sm[warp_in_blk];
    float* k = q + 16 * QSTR;
    float* v = k + 16 * QSTR;
    float* p = v + 16 * QSTR;                  // 16x16 probs

    int head = unit % NHh;
    int s = unit / NHh;
    int w = s & 31; s >>= 5;
    int h = s & 31;
    int b = s >> 5;

    int spatial = h * 32 + w;
    int fofs = head * 192;

    // Load q,k,v (T=16 x HD=64 each)
    for (int idx = lane; idx < 16 * 64; idx += 32) {
        int t = idx >> 6, d = idx & 63;
        size_t g = (size_t)((b * 16 + t) * 1024 + spatial) * F3 + fofs + d;
        q[t * QSTR + d] = qkv[g];
        k[t * QSTR + d] = qkv[g + 64];
        v[t * QSTR + d] = qkv[g + 128];
    }
    __syncwarp();

    // Scores: lane pair (2 lanes per tq), each lane does 8 tk
    int tq = lane >> 1;
    int tk0 = (lane & 1) * 8;
    float sc[8];
    #pragma unroll
    for (int j = 0; j < 8; j++) {
        float acc = 0.f;
        #pragma unroll
        for (int d = 0; d < 64; d++)
            acc += q[tq * QSTR + d] * k[(tk0 + j) * QSTR + d];
        sc[j] = acc * 0.125f;   // 1/sqrt(64)
    }
    float m = sc[0];
    #pragma unroll
    for (int j = 1; j < 8; j++) m = fmaxf(m, sc[j]);
    m = fmaxf(m, __shfl_xor_sync(0xffffffffu, m, 1));
    float sum = 0.f;
    #pragma unroll
    for (int j = 0; j < 8; j++) { sc[j] = __expf(sc[j] - m); sum += sc[j]; }
    sum += __shfl_xor_sync(0xffffffffu, sum, 1);
    float inv = 1.0f / sum;
    #pragma unroll
    for (int j = 0; j < 8; j++) p[tq * 16 + tk0 + j] = sc[j] * inv;
    __syncwarp();

    // o[t,d] = sum_tk p[t,tk] * v[tk,d]
    for (int idx = lane; idx < 16 * 64; idx += 32) {
        int t = idx >> 6, d = idx & 63;
        float acc = 0.f;
        #pragma unroll
        for (int tk = 0; tk < 16; tk++)
            acc += p[t * 16 + tk] * v[tk * QSTR + d];
        size_t g = (size_t)((b * 16 + t) * 1024 + spatial) * Cc + head * 64 + d;
        o[g] = acc;
    }
}

// ---------------------------------------------------------------------------
// Launch
// ---------------------------------------------------------------------------
extern "C" void kernel_launch(void* const* d_in, const int* in_sizes, int n_in,
                              void* d_out, int out_size) {
    const float* x     = (const float*)d_in[0];
    const float* ln1_w = (const float*)d_in[1];
    const float* ln1_b = (const float*)d_in[2];
    const float* Wqkv  = (const float*)d_in[3];
    const float* bqkv  = (const float*)d_in[4];
    const float* ln2_w = (const float*)d_in[5];
    const float* ln2_b = (const float*)d_in[6];
    const float* Wout  = (const float*)d_in[7];
    const float* bout  = (const float*)d_in[8];
    float* out = (float*)d_out;

    static __half *p_yh = nullptr, *p_wqh = nullptr, *p_woh = nullptr;
    static float *p_qkv = nullptr, *p_o = nullptr;
    if (!p_yh) {
        cudaGetSymbolAddress((void**)&p_yh, g_yh);
        cudaGetSymbolAddress((void**)&p_qkv, g_qkv);
        cudaGetSymbolAddress((void**)&p_o, g_o);
        cudaGetSymbolAddress((void**)&p_wqh, g_wqh);
        cudaGetSymbolAddress((void**)&p_woh, g_woh);
        cudaFuncSetAttribute(gemm_fp16<false>,
                             cudaFuncAttributeMaxDynamicSharedMemorySize, GEMM_SMEM_BYTES);
        cudaFuncSetAttribute(gemm_fp16<true>,
                             cudaFuncAttributeMaxDynamicSharedMemorySize, GEMM_SMEM_BYTES);
    }

    // 0) weights -> half
    {
        int n4q = (F3 * Cc) / 4, n4o = (Cc * Cc) / 4;
        f2h_kernel<<<(n4q + 255) / 256, 256>>>(Wqkv, p_wqh, n4q);
        f2h_kernel<<<(n4o + 255) / 256, 256>>>(Wout, p_woh, n4o);
    }

    // 1) LN1 -> half
    ln_kernel<<<NTOK, 192>>>(x, ln1_w, ln1_b, p_yh);

    // 2) QKV GEMM: (32768 x 2304)
    {
        dim3 grid(F3 / BN, NTOK / BM);     // 18 x 256
        gemm_fp16<false><<<grid, 256, GEMM_SMEM_BYTES>>>(p_yh, p_wqh, bqkv,
                                                         nullptr, p_qkv, F3, Cc);
    }

    // 3) Attention over time, per (b,h,w,head)
    {
        int nunits = Bb * Hh * Ww * NHh;   // 24576
        attn_kernel<<<nunits / 2, 64>>>(p_qkv, p_o);
    }

    // 4) LN2 -> half
    ln_kernel<<<NTOK, 192>>>(p_o, ln2_w, ln2_b, p_yh);

    // 5) Out GEMM + bias + residual: (32768 x 768)
    {
        dim3 grid(Cc / BN, NTOK / BM);     // 6 x 256
        gemm_fp16<true><<<grid, 256, GEMM_SMEM_BYTES>>>(p_yh, p_woh, bout,
                                                        x, out, Cc, Cc);
    }
}